// round 12
// baseline (speedup 1.0000x reference)
#include <cuda_runtime.h>
#include <cstdint>

// SINDy library: out[row] = [1, z(32), z_i*z_j (528), z_a*z_b*z_c (5984), sin(z)(32)]
// 8192 rows x 6577 cols fp32.
// R12 = R10 (4-wide branchless groups via fixup-redirect, ONE LDS.128 + ONE
// STG.128 per thread-iter, <=32 regs) at 128 threads/block: 16 blocks/SM so
// prologues of some blocks hide behind main loops of others.

#define NDIM     32
#define NPAIRS   528
#define NCOLS    6577
#define SBUF_PAD 600
#define NTHREADS 128
#define FIXBASE  (4 * SBUF_PAD)       // float idx of fixup region; 9600 B -> 16B aligned
#define FIX_MAX  320                  // >= 4 * (#boundary groups per phase)
#define SALL_N   (FIXBASE + FIX_MAX)
#define TB_PAD   1920                 // >= max ng4 (1644) + NTHREADS

static constexpr int pair_index(int i, int j) {
    return i * NDIM - (i * (i - 1)) / 2 + (j - i);
}

// ---- per-column (k, a): value = s_mul[a] * buf[k]; a=32 -> 1.0 ----
struct ColTbl { unsigned short e[NCOLS]; };
static constexpr ColTbl make_col_tbl() {
    ColTbl t{};
    for (int c = 0; c < 561; ++c)
        t.e[c] = (unsigned short)((unsigned)c | (32u << 10));
    {
        int col = 561;
        for (int a = 0; a < NDIM; ++a)
            for (int b = a; b < NDIM; ++b)
                for (int c = b; c < NDIM; ++c) {
                    unsigned k = 33u + (unsigned)pair_index(b, c);
                    t.e[col++] = (unsigned short)(k | ((unsigned)a << 10));
                }
    }
    for (int i = 0; i < NDIM; ++i)
        t.e[6545 + i] = (unsigned short)((unsigned)(561 + i) | (32u << 10));
    return t;
}
__device__ constexpr ColTbl G_COL = make_col_tbl();

// ---- per-column decomposition into s_m3[65] = [z(32), 1.0, sin(32)] ----
// value(col) = s_m3[m0] * s_m3[m1] * s_m3[m2]; packed m0 | m1<<7 | m2<<14.
static constexpr unsigned col_m3(int c) {
    if (c == 0)   return 32u | (32u << 7) | (32u << 14);
    if (c < 33)   return (unsigned)(c - 1) | (32u << 7) | (32u << 14);
    if (c < 561) {
        int p = c - 33, i = 0;
        while (p >= NDIM - i) { p -= NDIM - i; ++i; }
        return (unsigned)i | ((unsigned)(i + p) << 7) | (32u << 14);
    }
    if (c < 6545) {
        int r = c - 561, a = 0;
        while (true) {
            int m = NDIM - a, cnt = m * (m + 1) / 2;
            if (r < cnt) break;
            r -= cnt; ++a;
        }
        int b = a;
        while (r >= NDIM - b) { r -= NDIM - b; ++b; }
        return (unsigned)a | ((unsigned)b << 7) | ((unsigned)(b + r) << 14);
    }
    return (unsigned)(33 + (c - 6545)) | (32u << 7) | (32u << 14);
}

// ---- 4-wide group table with fixup redirection, per phase ----
struct Tbl4 {
    unsigned e[4][TB_PAD];        // low16: byte off into s_all; [16..30): za byte off
    unsigned fixsrc[4][FIX_MAX];  // packed m3 factors for fixup slot
    int      ng[4];
    int      nfix[4];
};

static constexpr Tbl4 make_tbl4() {
    ColTbl ct = make_col_tbl();
    Tbl4 t{};
    for (int ph = 0; ph < 4; ++ph) {
        int ng = (NCOLS - ph) / 4;
        t.ng[ph] = ng;
        int nf = 0;
        for (int g = 0; g < ng; ++g) {
            int c0 = ph + 4 * g;
            unsigned k0 = ct.e[c0] & 1023u;
            unsigned a0 = (unsigned)(ct.e[c0] >> 10);
            bool uniform = true;
            for (int j = 1; j < 4; ++j) {
                unsigned kj = ct.e[c0 + j] & 1023u;
                unsigned aj = (unsigned)(ct.e[c0 + j] >> 10);
                if (kj != k0 + (unsigned)j || aj != a0) { uniform = false; break; }
            }
            if (uniform) {
                unsigned P   = (4u - (k0 & 3u)) & 3u;
                unsigned off = (P * SBUF_PAD + k0 + P) * 4u;
                t.e[ph][g] = off | ((a0 * 4u) << 16);
            } else {
                // redirect: 4 consecutive fixup floats (16B aligned), za = 1.0 (idx 32)
                unsigned off = (unsigned)(FIXBASE + nf) * 4u;
                t.e[ph][g] = off | ((32u * 4u) << 16);
                for (int j = 0; j < 4; ++j)
                    t.fixsrc[ph][nf++] = col_m3(c0 + j);
            }
        }
        t.nfix[ph] = nf;   // ~264 max, < FIX_MAX
        for (int g = ng; g < TB_PAD; ++g) t.e[ph][g] = 0;
        for (int i = nf; i < FIX_MAX; ++i) t.fixsrc[ph][i] = 32u | (32u << 7) | (32u << 14);
    }
    return t;
}
__device__ constexpr Tbl4 G4 = make_tbl4();

struct PairTbl { unsigned short e[NPAIRS]; };
static constexpr PairTbl make_pair_tbl() {
    PairTbl t{};
    int p = 0;
    for (int i = 0; i < NDIM; ++i)
        for (int j = i; j < NDIM; ++j)
            t.e[p++] = (unsigned short)((unsigned)i | ((unsigned)j << 8));
    return t;
}
__device__ constexpr PairTbl G_PAIR = make_pair_tbl();

__global__ __launch_bounds__(NTHREADS) void sindy_library_kernel(
    const float* __restrict__ z, float* __restrict__ out)
{
    // s_all: 4 shifted buf copies (copy P at P*SBUF_PAD; s_copyP[P+k] = buf[k]),
    // then the fixup region at FIXBASE. LDS.128 at (k0+P), P=(-k0)&3: 16B-aligned.
    __shared__ __align__(16) float s_all[SALL_N];
    __shared__ float s_mul[NDIM + 1];   // z..., 1.0f at [32]
    __shared__ float s_m3[65];          // z(32), 1.0 at [32], sin at [33..64]

    const int row = blockIdx.x;
    const int t   = threadIdx.x;

    if (t < NDIM) {
        float v  = z[row * NDIM + t];
        float sv = __sinf(v);
        s_mul[t]     = v;
        s_m3[t]      = v;
        s_m3[33 + t] = sv;
        #pragma unroll
        for (int P = 0; P < 4; ++P) {
            s_all[P * SBUF_PAD + P + 1 + t]   = v;
            s_all[P * SBUF_PAD + P + 561 + t] = sv;
        }
    } else if (t == NDIM) {
        s_mul[NDIM] = 1.0f;
        s_m3[32]    = 1.0f;
        #pragma unroll
        for (int P = 0; P < 4; ++P) s_all[P * SBUF_PAD + P] = 1.0f;
    }
    __syncthreads();

    const int ph = (4 - (row & 3)) & 3;

    // Pair products into all 4 shifted copies.
    for (int p = t; p < NPAIRS; p += NTHREADS) {
        unsigned ij = (unsigned)G_PAIR.e[p];
        float v = s_mul[ij & 31u] * s_mul[(ij >> 8) & 31u];
        #pragma unroll
        for (int P = 0; P < 4; ++P) s_all[P * SBUF_PAD + P + 33 + p] = v;
    }
    // Fixup values: pre-multiplied products of up to 3 factors (za folded in).
    {
        const int nfix = G4.nfix[ph];
        for (int f = t; f < nfix; f += NTHREADS) {
            unsigned s = __ldg(&G4.fixsrc[ph][f]);
            s_all[FIXBASE + f] =
                s_m3[s & 127u] * s_m3[(s >> 7) & 127u] * s_m3[(s >> 14) & 127u];
        }
    }
    __syncthreads();

    float* __restrict__ o = out + (size_t)row * NCOLS;

    // Head scalars (< 4 cols)
    if (t < ph) {
        unsigned e = (unsigned)G_COL.e[t];
        o[t] = s_mul[e >> 10] * s_all[e & 1023u];
    }

    const int ng = G4.ng[ph];
    const unsigned* __restrict__ tb = &G4.e[ph][0];
    const char* __restrict__ sc = (const char*)&s_all[0];
    const char* __restrict__ sm = (const char*)&s_mul[0];

    unsigned e = __ldg(&tb[t]);                   // prefetch first entry
    for (int g = t; g < ng; g += NTHREADS) {
        unsigned en = __ldg(&tb[g + NTHREADS]);   // padded: always in-bounds

        float4 b  = *(const float4*)(sc + (e & 0xFFFFu));
        float  za = *(const float*)(sm + (e >> 16));
        float4 r  = make_float4(za * b.x, za * b.y, za * b.z, za * b.w);

        __stcs((float4*)(o + ph + 4 * g), r);     // one 16B store per iter
        e = en;
    }

    // Tail scalars (< 4 cols)
    {
        int c = ph + 4 * ng + t;
        if (c < NCOLS) {
            unsigned ee = (unsigned)G_COL.e[c];
            o[c] = s_mul[ee >> 10] * s_all[ee & 1023u];
        }
    }
}

extern "C" void kernel_launch(void* const* d_in, const int* in_sizes, int n_in,
                              void* d_out, int out_size) {
    const float* z   = (const float*)d_in[0];
    float*       out = (float*)d_out;
    sindy_library_kernel<<<8192, NTHREADS>>>(z, out);
}

// round 13
// speedup vs baseline: 1.0244x; 1.0244x over previous
#include <cuda_runtime.h>
#include <cstdint>

// SINDy library: out[row] = [1, z(32), z_i*z_j (528), z_a*z_b*z_c (5984), sin(z)(32)]
// 8192 rows x 6577 cols fp32.
// R13 = R10 (4-wide branchless groups via fixup-redirect, one LDS.128 + one
// STG.128 per iteration chain, 256 thr) + manual 2x unroll: two INDEPENDENT
// LDS->FMUL->STG chains per loop body (stores ~1KB apart) to double per-warp
// LDS MLP. __launch_bounds__(256, 8) pins occupancy.

#define NDIM     32
#define NPAIRS   528
#define NCOLS    6577
#define SBUF_PAD 600
#define NTHREADS 256
#define FIXBASE  (4 * SBUF_PAD)       // float idx of fixup region; 9600 B -> 16B aligned
#define FIX_MAX  320
#define SALL_N   (FIXBASE + FIX_MAX)
#define TB_PAD   2200                 // >= max ng4 (1644) + 2*NTHREADS pad

static constexpr int pair_index(int i, int j) {
    return i * NDIM - (i * (i - 1)) / 2 + (j - i);
}

// ---- per-column (k, a): value = s_mul[a] * buf[k]; a=32 -> 1.0 ----
struct ColTbl { unsigned short e[NCOLS]; };
static constexpr ColTbl make_col_tbl() {
    ColTbl t{};
    for (int c = 0; c < 561; ++c)
        t.e[c] = (unsigned short)((unsigned)c | (32u << 10));
    {
        int col = 561;
        for (int a = 0; a < NDIM; ++a)
            for (int b = a; b < NDIM; ++b)
                for (int c = b; c < NDIM; ++c) {
                    unsigned k = 33u + (unsigned)pair_index(b, c);
                    t.e[col++] = (unsigned short)(k | ((unsigned)a << 10));
                }
    }
    for (int i = 0; i < NDIM; ++i)
        t.e[6545 + i] = (unsigned short)((unsigned)(561 + i) | (32u << 10));
    return t;
}
__device__ constexpr ColTbl G_COL = make_col_tbl();

// ---- per-column decomposition into s_m3[65] = [z(32), 1.0, sin(32)] ----
static constexpr unsigned col_m3(int c) {
    if (c == 0)   return 32u | (32u << 7) | (32u << 14);
    if (c < 33)   return (unsigned)(c - 1) | (32u << 7) | (32u << 14);
    if (c < 561) {
        int p = c - 33, i = 0;
        while (p >= NDIM - i) { p -= NDIM - i; ++i; }
        return (unsigned)i | ((unsigned)(i + p) << 7) | (32u << 14);
    }
    if (c < 6545) {
        int r = c - 561, a = 0;
        while (true) {
            int m = NDIM - a, cnt = m * (m + 1) / 2;
            if (r < cnt) break;
            r -= cnt; ++a;
        }
        int b = a;
        while (r >= NDIM - b) { r -= NDIM - b; ++b; }
        return (unsigned)a | ((unsigned)b << 7) | ((unsigned)(b + r) << 14);
    }
    return (unsigned)(33 + (c - 6545)) | (32u << 7) | (32u << 14);
}

// ---- 4-wide group table with fixup redirection, per phase ----
struct Tbl4 {
    unsigned e[4][TB_PAD];        // low16: byte off into s_all; [16..30): za byte off
    unsigned fixsrc[4][FIX_MAX];
    int      ng[4];
    int      nfix[4];
};

static constexpr Tbl4 make_tbl4() {
    ColTbl ct = make_col_tbl();
    Tbl4 t{};
    for (int ph = 0; ph < 4; ++ph) {
        int ng = (NCOLS - ph) / 4;
        t.ng[ph] = ng;
        int nf = 0;
        for (int g = 0; g < ng; ++g) {
            int c0 = ph + 4 * g;
            unsigned k0 = ct.e[c0] & 1023u;
            unsigned a0 = (unsigned)(ct.e[c0] >> 10);
            bool uniform = true;
            for (int j = 1; j < 4; ++j) {
                unsigned kj = ct.e[c0 + j] & 1023u;
                unsigned aj = (unsigned)(ct.e[c0 + j] >> 10);
                if (kj != k0 + (unsigned)j || aj != a0) { uniform = false; break; }
            }
            if (uniform) {
                unsigned P   = (4u - (k0 & 3u)) & 3u;
                unsigned off = (P * SBUF_PAD + k0 + P) * 4u;
                t.e[ph][g] = off | ((a0 * 4u) << 16);
            } else {
                unsigned off = (unsigned)(FIXBASE + nf) * 4u;
                t.e[ph][g] = off | ((32u * 4u) << 16);
                for (int j = 0; j < 4; ++j)
                    t.fixsrc[ph][nf++] = col_m3(c0 + j);
            }
        }
        t.nfix[ph] = nf;
        for (int g = ng; g < TB_PAD; ++g) t.e[ph][g] = 0;  // pad (safe dummy)
        for (int i = nf; i < FIX_MAX; ++i) t.fixsrc[ph][i] = 32u | (32u << 7) | (32u << 14);
    }
    return t;
}
__device__ constexpr Tbl4 G4 = make_tbl4();

struct PairTbl { unsigned short e[NPAIRS]; };
static constexpr PairTbl make_pair_tbl() {
    PairTbl t{};
    int p = 0;
    for (int i = 0; i < NDIM; ++i)
        for (int j = i; j < NDIM; ++j)
            t.e[p++] = (unsigned short)((unsigned)i | ((unsigned)j << 8));
    return t;
}
__device__ constexpr PairTbl G_PAIR = make_pair_tbl();

__global__ __launch_bounds__(NTHREADS, 8) void sindy_library_kernel(
    const float* __restrict__ z, float* __restrict__ out)
{
    __shared__ __align__(16) float s_all[SALL_N];
    __shared__ float s_mul[NDIM + 1];
    __shared__ float s_m3[65];

    const int row = blockIdx.x;
    const int t   = threadIdx.x;

    if (t < NDIM) {
        float v  = z[row * NDIM + t];
        float sv = __sinf(v);
        s_mul[t]     = v;
        s_m3[t]      = v;
        s_m3[33 + t] = sv;
        #pragma unroll
        for (int P = 0; P < 4; ++P) {
            s_all[P * SBUF_PAD + P + 1 + t]   = v;
            s_all[P * SBUF_PAD + P + 561 + t] = sv;
        }
    } else if (t == NDIM) {
        s_mul[NDIM] = 1.0f;
        s_m3[32]    = 1.0f;
        #pragma unroll
        for (int P = 0; P < 4; ++P) s_all[P * SBUF_PAD + P] = 1.0f;
    }
    __syncthreads();

    const int ph = (4 - (row & 3)) & 3;

    for (int p = t; p < NPAIRS; p += NTHREADS) {
        unsigned ij = (unsigned)G_PAIR.e[p];
        float v = s_mul[ij & 31u] * s_mul[(ij >> 8) & 31u];
        #pragma unroll
        for (int P = 0; P < 4; ++P) s_all[P * SBUF_PAD + P + 33 + p] = v;
    }
    {
        const int nfix = G4.nfix[ph];
        for (int f = t; f < nfix; f += NTHREADS) {
            unsigned s = __ldg(&G4.fixsrc[ph][f]);
            s_all[FIXBASE + f] =
                s_m3[s & 127u] * s_m3[(s >> 7) & 127u] * s_m3[(s >> 14) & 127u];
        }
    }
    __syncthreads();

    float* __restrict__ o = out + (size_t)row * NCOLS;

    if (t < ph) {
        unsigned e = (unsigned)G_COL.e[t];
        o[t] = s_mul[e >> 10] * s_all[e & 1023u];
    }

    const int ng = G4.ng[ph];
    const unsigned* __restrict__ tb = &G4.e[ph][0];
    const char* __restrict__ sc = (const char*)&s_all[0];
    const char* __restrict__ sm = (const char*)&s_mul[0];

    // 2x-unrolled main loop: two independent LDS->FMUL->STG chains per body.
    // ng for 256 threads is 6.4 iters; unrolled body covers g and g+256.
    unsigned e0 = __ldg(&tb[t]);
    unsigned e1 = __ldg(&tb[t + NTHREADS]);
    int g = t;
    for (; g + NTHREADS < ng; g += 2 * NTHREADS) {
        unsigned f0 = __ldg(&tb[g + 2 * NTHREADS]);       // padded: in-bounds
        unsigned f1 = __ldg(&tb[g + 3 * NTHREADS]);

        float4 b0 = *(const float4*)(sc + (e0 & 0xFFFFu));
        float4 b1 = *(const float4*)(sc + (e1 & 0xFFFFu));
        float  za0 = *(const float*)(sm + (e0 >> 16));
        float  za1 = *(const float*)(sm + (e1 >> 16));

        float4 r0 = make_float4(za0 * b0.x, za0 * b0.y, za0 * b0.z, za0 * b0.w);
        __stcs((float4*)(o + ph + 4 * g), r0);

        float4 r1 = make_float4(za1 * b1.x, za1 * b1.y, za1 * b1.z, za1 * b1.w);
        __stcs((float4*)(o + ph + 4 * (g + NTHREADS)), r1);

        e0 = f0;
        e1 = f1;
    }
    // Remainder (0 or 1 group for this thread)
    if (g < ng) {
        float4 b  = *(const float4*)(sc + (e0 & 0xFFFFu));
        float  za = *(const float*)(sm + (e0 >> 16));
        float4 r  = make_float4(za * b.x, za * b.y, za * b.z, za * b.w);
        __stcs((float4*)(o + ph + 4 * g), r);
    }

    // Tail scalars (< 4 cols)
    {
        int c = ph + 4 * ng + t;
        if (c < NCOLS) {
            unsigned ee = (unsigned)G_COL.e[c];
            o[c] = s_mul[ee >> 10] * s_all[ee & 1023u];
        }
    }
}

extern "C" void kernel_launch(void* const* d_in, const int* in_sizes, int n_in,
                              void* d_out, int out_size) {
    const float* z   = (const float*)d_in[0];
    float*       out = (float*)d_out;
    sindy_library_kernel<<<8192, NTHREADS>>>(z, out);
}

// round 14
// speedup vs baseline: 1.0662x; 1.0408x over previous
#include <cuda_runtime.h>
#include <cstdint>

// SINDy library: out[row] = [1, z(32), z_i*z_j (528), z_a*z_b*z_c (5984), sin(z)(32)]
// 8192 rows x 6577 cols fp32.
// R14 = R13 main loop (4-wide branchless groups via fixup-redirect, unroll-2,
// one LDS.128 + one STG.128 per chain) + SINGLE-BARRIER prologue: pair build
// and fixup build read z directly via __ldg (L1-hot 128B line) instead of smem,
// so z/sin replication, pairs and fixups all run concurrently before one bar.

#define NDIM     32
#define NPAIRS   528
#define NCOLS    6577
#define SBUF_PAD 600
#define NTHREADS 256
#define FIXBASE  (4 * SBUF_PAD)       // float idx of fixup region; 9600 B -> 16B aligned
#define FIX_MAX  320
#define SALL_N   (FIXBASE + FIX_MAX)
#define TB_PAD   2200                 // >= max ng4 (1644) + 2*NTHREADS pad

static constexpr int pair_index(int i, int j) {
    return i * NDIM - (i * (i - 1)) / 2 + (j - i);
}

// ---- per-column (k, a): value = s_mul[a] * buf[k]; a=32 -> 1.0 ----
struct ColTbl { unsigned short e[NCOLS]; };
static constexpr ColTbl make_col_tbl() {
    ColTbl t{};
    for (int c = 0; c < 561; ++c)
        t.e[c] = (unsigned short)((unsigned)c | (32u << 10));
    {
        int col = 561;
        for (int a = 0; a < NDIM; ++a)
            for (int b = a; b < NDIM; ++b)
                for (int c = b; c < NDIM; ++c) {
                    unsigned k = 33u + (unsigned)pair_index(b, c);
                    t.e[col++] = (unsigned short)(k | ((unsigned)a << 10));
                }
    }
    for (int i = 0; i < NDIM; ++i)
        t.e[6545 + i] = (unsigned short)((unsigned)(561 + i) | (32u << 10));
    return t;
}
__device__ constexpr ColTbl G_COL = make_col_tbl();

// ---- per-column decomposition: factors m in [0,32]=z/1.0, [33,64]=sin ----
static constexpr unsigned col_m3(int c) {
    if (c == 0)   return 32u | (32u << 7) | (32u << 14);
    if (c < 33)   return (unsigned)(c - 1) | (32u << 7) | (32u << 14);
    if (c < 561) {
        int p = c - 33, i = 0;
        while (p >= NDIM - i) { p -= NDIM - i; ++i; }
        return (unsigned)i | ((unsigned)(i + p) << 7) | (32u << 14);
    }
    if (c < 6545) {
        int r = c - 561, a = 0;
        while (true) {
            int m = NDIM - a, cnt = m * (m + 1) / 2;
            if (r < cnt) break;
            r -= cnt; ++a;
        }
        int b = a;
        while (r >= NDIM - b) { r -= NDIM - b; ++b; }
        return (unsigned)a | ((unsigned)b << 7) | ((unsigned)(b + r) << 14);
    }
    return (unsigned)(33 + (c - 6545)) | (32u << 7) | (32u << 14);
}

// ---- 4-wide group table with fixup redirection, per phase ----
struct Tbl4 {
    unsigned e[4][TB_PAD];        // low16: byte off into s_all; [16..30): za byte off
    unsigned fixsrc[4][FIX_MAX];
    int      ng[4];
    int      nfix[4];
};

static constexpr Tbl4 make_tbl4() {
    ColTbl ct = make_col_tbl();
    Tbl4 t{};
    for (int ph = 0; ph < 4; ++ph) {
        int ng = (NCOLS - ph) / 4;
        t.ng[ph] = ng;
        int nf = 0;
        for (int g = 0; g < ng; ++g) {
            int c0 = ph + 4 * g;
            unsigned k0 = ct.e[c0] & 1023u;
            unsigned a0 = (unsigned)(ct.e[c0] >> 10);
            bool uniform = true;
            for (int j = 1; j < 4; ++j) {
                unsigned kj = ct.e[c0 + j] & 1023u;
                unsigned aj = (unsigned)(ct.e[c0 + j] >> 10);
                if (kj != k0 + (unsigned)j || aj != a0) { uniform = false; break; }
            }
            if (uniform) {
                unsigned P   = (4u - (k0 & 3u)) & 3u;
                unsigned off = (P * SBUF_PAD + k0 + P) * 4u;
                t.e[ph][g] = off | ((a0 * 4u) << 16);
            } else {
                unsigned off = (unsigned)(FIXBASE + nf) * 4u;
                t.e[ph][g] = off | ((32u * 4u) << 16);
                for (int j = 0; j < 4; ++j)
                    t.fixsrc[ph][nf++] = col_m3(c0 + j);
            }
        }
        t.nfix[ph] = nf;
        for (int g = ng; g < TB_PAD; ++g) t.e[ph][g] = 0;
        for (int i = nf; i < FIX_MAX; ++i) t.fixsrc[ph][i] = 32u | (32u << 7) | (32u << 14);
    }
    return t;
}
__device__ constexpr Tbl4 G4 = make_tbl4();

struct PairTbl { unsigned short e[NPAIRS]; };
static constexpr PairTbl make_pair_tbl() {
    PairTbl t{};
    int p = 0;
    for (int i = 0; i < NDIM; ++i)
        for (int j = i; j < NDIM; ++j)
            t.e[p++] = (unsigned short)((unsigned)i | ((unsigned)j << 8));
    return t;
}
__device__ constexpr PairTbl G_PAIR = make_pair_tbl();

// Factor fetch straight from global z (L1-hot line); m: 0-31 z, 32 -> 1.0, 33-64 sin.
__device__ __forceinline__ float fac(const float* __restrict__ zr, unsigned m) {
    if (m < 32u)  return __ldg(zr + m);
    if (m == 32u) return 1.0f;
    return __sinf(__ldg(zr + (m - 33u)));
}

__global__ __launch_bounds__(NTHREADS, 8) void sindy_library_kernel(
    const float* __restrict__ z, float* __restrict__ out)
{
    __shared__ __align__(16) float s_all[SALL_N];
    __shared__ float s_mul[NDIM + 1];   // z..., 1.0f at [32] (main-loop za source)

    const int row = blockIdx.x;
    const int t   = threadIdx.x;
    const int ph  = (4 - (row & 3)) & 3;
    const float* __restrict__ zr = z + (size_t)row * NDIM;

    // ---- single-phase prologue: three independent build tasks, ONE barrier ----
    // (1) z / sin / 1.0 replication into the 4 shifted copies + s_mul (t < 33)
    if (t < NDIM) {
        float v  = __ldg(zr + t);
        float sv = __sinf(v);
        s_mul[t] = v;
        #pragma unroll
        for (int P = 0; P < 4; ++P) {
            s_all[P * SBUF_PAD + P + 1 + t]   = v;
            s_all[P * SBUF_PAD + P + 561 + t] = sv;
        }
    } else if (t == NDIM) {
        s_mul[NDIM] = 1.0f;
        #pragma unroll
        for (int P = 0; P < 4; ++P) s_all[P * SBUF_PAD + P] = 1.0f;
    }

    // (2) pair products: read z via LDG (no smem dependency)
    for (int p = t; p < NPAIRS; p += NTHREADS) {
        unsigned ij = (unsigned)G_PAIR.e[p];
        float v = __ldg(zr + (ij & 31u)) * __ldg(zr + ((ij >> 8) & 31u));
        #pragma unroll
        for (int P = 0; P < 4; ++P) s_all[P * SBUF_PAD + P + 33 + p] = v;
    }

    // (3) fixup values: factors via LDG / recomputed sin (no smem dependency)
    {
        const int nfix = G4.nfix[ph];
        for (int f = t; f < nfix; f += NTHREADS) {
            unsigned s = __ldg(&G4.fixsrc[ph][f]);
            s_all[FIXBASE + f] =
                fac(zr, s & 127u) * fac(zr, (s >> 7) & 127u) * fac(zr, (s >> 14) & 127u);
        }
    }
    __syncthreads();   // the only block-wide barrier

    float* __restrict__ o = out + (size_t)row * NCOLS;

    // Head scalars (< 4 cols)
    if (t < ph) {
        unsigned e = (unsigned)G_COL.e[t];
        o[t] = s_mul[e >> 10] * s_all[e & 1023u];
    }

    const int ng = G4.ng[ph];
    const unsigned* __restrict__ tb = &G4.e[ph][0];
    const char* __restrict__ sc = (const char*)&s_all[0];
    const char* __restrict__ sm = (const char*)&s_mul[0];

    // 2x-unrolled main loop: two independent LDS->FMUL->STG chains per body.
    unsigned e0 = __ldg(&tb[t]);
    unsigned e1 = __ldg(&tb[t + NTHREADS]);
    int g = t;
    for (; g + NTHREADS < ng; g += 2 * NTHREADS) {
        unsigned f0 = __ldg(&tb[g + 2 * NTHREADS]);   // padded: in-bounds
        unsigned f1 = __ldg(&tb[g + 3 * NTHREADS]);

        float4 b0 = *(const float4*)(sc + (e0 & 0xFFFFu));
        float4 b1 = *(const float4*)(sc + (e1 & 0xFFFFu));
        float  za0 = *(const float*)(sm + (e0 >> 16));
        float  za1 = *(const float*)(sm + (e1 >> 16));

        float4 r0 = make_float4(za0 * b0.x, za0 * b0.y, za0 * b0.z, za0 * b0.w);
        __stcs((float4*)(o + ph + 4 * g), r0);

        float4 r1 = make_float4(za1 * b1.x, za1 * b1.y, za1 * b1.z, za1 * b1.w);
        __stcs((float4*)(o + ph + 4 * (g + NTHREADS)), r1);

        e0 = f0;
        e1 = f1;
    }
    if (g < ng) {
        float4 b  = *(const float4*)(sc + (e0 & 0xFFFFu));
        float  za = *(const float*)(sm + (e0 >> 16));
        float4 r  = make_float4(za * b.x, za * b.y, za * b.z, za * b.w);
        __stcs((float4*)(o + ph + 4 * g), r);
    }

    // Tail scalars (< 4 cols)
    {
        int c = ph + 4 * ng + t;
        if (c < NCOLS) {
            unsigned ee = (unsigned)G_COL.e[c];
            o[c] = s_mul[ee >> 10] * s_all[ee & 1023u];
        }
    }
}

extern "C" void kernel_launch(void* const* d_in, const int* in_sizes, int n_in,
                              void* d_out, int out_size) {
    const float* z   = (const float*)d_in[0];
    float*       out = (float*)d_out;
    sindy_library_kernel<<<8192, NTHREADS>>>(z, out);
}